// round 2
// baseline (speedup 1.0000x reference)
#include <cuda_runtime.h>

#define FID 65536
#define BATCH 2048
#define ROW_V4 (FID / 4)   // 16384 float4 per row

__device__ float        g_row_loss[BATCH];
__device__ unsigned int g_done_count;      // zero-init; atomicInc wraps -> replay-safe

__global__ __launch_bounds__(256) void fused_lr_kernel(
    const float* __restrict__ gate,
    const float* __restrict__ bias,
    const float* __restrict__ gbias,
    const float* __restrict__ label,
    float* __restrict__ logits,
    float* __restrict__ pred,
    float* __restrict__ loss)
{
    const int row = blockIdx.x;
    const float4* __restrict__ g = reinterpret_cast<const float4*>(gate + (size_t)row * FID);
    const float4* __restrict__ b = reinterpret_cast<const float4*>(bias);

    float acc = 0.0f;
    // 256 threads x 64 iters, coalesced; gate streamed (no reuse), bias cached (L2-hot)
    #pragma unroll 4
    for (int i = threadIdx.x; i < ROW_V4; i += 256) {
        float4 gv = __ldcs(&g[i]);
        float4 bv = __ldg(&b[i]);
        acc = fmaf(gv.x, bv.x, acc);
        acc = fmaf(gv.y, bv.y, acc);
        acc = fmaf(gv.z, bv.z, acc);
        acc = fmaf(gv.w, bv.w, acc);
    }

    // block reduce (fixed order -> deterministic)
    #pragma unroll
    for (int off = 16; off > 0; off >>= 1)
        acc += __shfl_down_sync(0xFFFFFFFFu, acc, off);

    __shared__ float smem[8];
    const int lane = threadIdx.x & 31;
    const int wid  = threadIdx.x >> 5;
    if (lane == 0) smem[wid] = acc;
    __syncthreads();

    __shared__ bool s_is_last;
    if (threadIdx.x == 0) {
        float v = smem[0] + smem[1] + smem[2] + smem[3]
                + smem[4] + smem[5] + smem[6] + smem[7];
        float z = v + gbias[0];
        logits[row] = z;
        pred[row]   = 1.0f / (1.0f + __expf(-z));
        float y = label[row];
        g_row_loss[row] = fmaxf(z, 0.0f) - z * y + log1pf(expf(-fabsf(z)));

        __threadfence();
        // wraps: old == BATCH-1 -> stores 0 (ready for next graph replay)
        unsigned int ticket = atomicInc(&g_done_count, BATCH - 1);
        s_is_last = (ticket == BATCH - 1);
    }
    __syncthreads();

    if (s_is_last) {
        // deterministic fixed-order reduction of 2048 per-row losses
        float lsum = 0.0f;
        #pragma unroll
        for (int k = 0; k < BATCH / 256; k++)
            lsum += g_row_loss[threadIdx.x + k * 256];

        #pragma unroll
        for (int off = 16; off > 0; off >>= 1)
            lsum += __shfl_down_sync(0xFFFFFFFFu, lsum, off);

        __shared__ float smem2[8];
        if (lane == 0) smem2[wid] = lsum;
        __syncthreads();
        if (threadIdx.x == 0) {
            loss[0] = smem2[0] + smem2[1] + smem2[2] + smem2[3]
                    + smem2[4] + smem2[5] + smem2[6] + smem2[7];
        }
    }
}

extern "C" void kernel_launch(void* const* d_in, const int* in_sizes, int n_in,
                              void* d_out, int out_size)
{
    // Inputs: 0 gate [2048,65536] f32, 1 sparse_bias [65536] f32,
    //         2 global_bias [1] f32, 3 label [2048] f32
    const float* gate  = (const float*)d_in[0];
    const float* bias  = (const float*)d_in[1];
    const float* gbias = (const float*)d_in[2];
    const float* label = (const float*)d_in[3];

    // Output: logits[2048], pred[2048], loss[1]
    float* out    = (float*)d_out;
    float* logits = out;
    float* pred   = out + BATCH;
    float* loss   = out + 2 * BATCH;

    fused_lr_kernel<<<BATCH, 256>>>(gate, bias, gbias, label, logits, pred, loss);
}

// round 4
// speedup vs baseline: 1.0935x; 1.0935x over previous
#include <cuda_runtime.h>

#define FID 65536
#define BATCH 2048
#define ROW_V4 (FID / 4)   // 16384 float4 per row

__device__ float        g_row_loss[BATCH];
__device__ unsigned int g_done_count;      // zero-init; atomicInc wraps -> replay-safe

__global__ __launch_bounds__(256, 8) void fused_lr_kernel(
    const float* __restrict__ gate,
    const float* __restrict__ bias,
    const float* __restrict__ gbias,
    const float* __restrict__ label,
    float* __restrict__ logits,
    float* __restrict__ pred,
    float* __restrict__ loss)
{
    const int row = blockIdx.x;
    const float4* __restrict__ g = reinterpret_cast<const float4*>(gate + (size_t)row * FID);
    const float4* __restrict__ b = reinterpret_cast<const float4*>(bias);

    // 256 threads x 16384 float4 per row -> 64 iters/thread, unroll-2 pairs,
    // two accumulators; fits the 32-reg budget for 8 blocks/SM residency.
    float acc0 = 0.0f, acc1 = 0.0f;
    #pragma unroll 2
    for (int i = threadIdx.x; i < ROW_V4; i += 2 * 256) {
        float4 gv0 = g[i];
        float4 bv0 = b[i];
        float4 gv1 = g[i + 256];
        float4 bv1 = b[i + 256];
        acc0 = fmaf(gv0.x, bv0.x, acc0);
        acc0 = fmaf(gv0.y, bv0.y, acc0);
        acc0 = fmaf(gv0.z, bv0.z, acc0);
        acc0 = fmaf(gv0.w, bv0.w, acc0);
        acc1 = fmaf(gv1.x, bv1.x, acc1);
        acc1 = fmaf(gv1.y, bv1.y, acc1);
        acc1 = fmaf(gv1.z, bv1.z, acc1);
        acc1 = fmaf(gv1.w, bv1.w, acc1);
    }
    float acc = acc0 + acc1;

    // block reduce (fixed order -> deterministic)
    #pragma unroll
    for (int off = 16; off > 0; off >>= 1)
        acc += __shfl_down_sync(0xFFFFFFFFu, acc, off);

    __shared__ float smem[8];
    const int lane = threadIdx.x & 31;
    const int wid  = threadIdx.x >> 5;
    if (lane == 0) smem[wid] = acc;
    __syncthreads();

    __shared__ bool s_is_last;
    if (threadIdx.x == 0) {
        float v = smem[0] + smem[1] + smem[2] + smem[3]
                + smem[4] + smem[5] + smem[6] + smem[7];
        float z = v + gbias[0];
        logits[row] = z;
        pred[row]   = 1.0f / (1.0f + __expf(-z));
        float y = label[row];
        g_row_loss[row] = fmaxf(z, 0.0f) - z * y + log1pf(expf(-fabsf(z)));

        __threadfence();
        // wraps: old == BATCH-1 -> stores 0 (ready for next graph replay)
        unsigned int ticket = atomicInc(&g_done_count, BATCH - 1);
        s_is_last = (ticket == BATCH - 1);
    }
    __syncthreads();

    if (s_is_last) {
        // deterministic fixed-order reduction of 2048 per-row losses
        float lsum = 0.0f;
        #pragma unroll
        for (int k = 0; k < BATCH / 256; k++)
            lsum += g_row_loss[threadIdx.x + k * 256];

        #pragma unroll
        for (int off = 16; off > 0; off >>= 1)
            lsum += __shfl_down_sync(0xFFFFFFFFu, lsum, off);

        __shared__ float smem2[8];
        if (lane == 0) smem2[wid] = lsum;
        __syncthreads();
        if (threadIdx.x == 0) {
            loss[0] = smem2[0] + smem2[1] + smem2[2] + smem2[3]
                    + smem2[4] + smem2[5] + smem2[6] + smem2[7];
        }
    }
}

extern "C" void kernel_launch(void* const* d_in, const int* in_sizes, int n_in,
                              void* d_out, int out_size)
{
    // Inputs: 0 gate [2048,65536] f32, 1 sparse_bias [65536] f32,
    //         2 global_bias [1] f32, 3 label [2048] f32
    const float* gate  = (const float*)d_in[0];
    const float* bias  = (const float*)d_in[1];
    const float* gbias = (const float*)d_in[2];
    const float* label = (const float*)d_in[3];

    // Output: logits[2048], pred[2048], loss[1]
    float* out    = (float*)d_out;
    float* logits = out;
    float* pred   = out + BATCH;
    float* loss   = out + 2 * BATCH;

    fused_lr_kernel<<<BATCH, 256>>>(gate, bias, gbias, label, logits, pred, loss);
}

// round 5
// speedup vs baseline: 1.0994x; 1.0054x over previous
#include <cuda_runtime.h>

#define FID 65536
#define BATCH 2048
#define ROW_V4 (FID / 4)        // 16384 float4 per row
#define NBLK (BATCH / 2)        // 2 rows per block -> 1024 blocks (single wave)

__device__ float        g_row_loss[BATCH];
__device__ unsigned int g_done_count;      // zero-init; atomicInc wraps -> replay-safe

__global__ __launch_bounds__(256, 8) void fused_lr2_kernel(
    const float* __restrict__ gate,
    const float* __restrict__ bias,
    const float* __restrict__ gbias,
    const float* __restrict__ label,
    float* __restrict__ logits,
    float* __restrict__ pred,
    float* __restrict__ loss)
{
    const int r0 = blockIdx.x * 2;       // this block handles rows r0, r0+1
    const float4* __restrict__ g0 = reinterpret_cast<const float4*>(gate + (size_t)r0 * FID);
    const float4* __restrict__ g1 = g0 + ROW_V4;
    const float4* __restrict__ b  = reinterpret_cast<const float4*>(bias);

    // One bias load amortized over two gate rows: 3 loads, 8 FMAs per iter.
    float acc0 = 0.0f, acc1 = 0.0f;
    for (int i = threadIdx.x; i < ROW_V4; i += 256) {
        float4 bv = b[i];
        float4 v0 = g0[i];
        float4 v1 = g1[i];
        acc0 = fmaf(v0.x, bv.x, acc0);
        acc0 = fmaf(v0.y, bv.y, acc0);
        acc0 = fmaf(v0.z, bv.z, acc0);
        acc0 = fmaf(v0.w, bv.w, acc0);
        acc1 = fmaf(v1.x, bv.x, acc1);
        acc1 = fmaf(v1.y, bv.y, acc1);
        acc1 = fmaf(v1.z, bv.z, acc1);
        acc1 = fmaf(v1.w, bv.w, acc1);
    }

    // block reduce both accumulators (fixed order -> deterministic)
    #pragma unroll
    for (int off = 16; off > 0; off >>= 1) {
        acc0 += __shfl_down_sync(0xFFFFFFFFu, acc0, off);
        acc1 += __shfl_down_sync(0xFFFFFFFFu, acc1, off);
    }

    __shared__ float smem0[8], smem1[8];
    const int lane = threadIdx.x & 31;
    const int wid  = threadIdx.x >> 5;
    if (lane == 0) { smem0[wid] = acc0; smem1[wid] = acc1; }
    __syncthreads();

    __shared__ bool s_is_last;
    if (threadIdx.x == 0) {
        float gb = gbias[0];
        float z0 = smem0[0] + smem0[1] + smem0[2] + smem0[3]
                 + smem0[4] + smem0[5] + smem0[6] + smem0[7] + gb;
        float z1 = smem1[0] + smem1[1] + smem1[2] + smem1[3]
                 + smem1[4] + smem1[5] + smem1[6] + smem1[7] + gb;

        logits[r0]     = z0;
        logits[r0 + 1] = z1;
        pred[r0]       = 1.0f / (1.0f + __expf(-z0));
        pred[r0 + 1]   = 1.0f / (1.0f + __expf(-z1));
        float y0 = label[r0], y1 = label[r0 + 1];
        g_row_loss[r0]     = fmaxf(z0, 0.0f) - z0 * y0 + log1pf(expf(-fabsf(z0)));
        g_row_loss[r0 + 1] = fmaxf(z1, 0.0f) - z1 * y1 + log1pf(expf(-fabsf(z1)));

        __threadfence();
        // wraps: old == NBLK-1 -> stores 0 (ready for next graph replay)
        unsigned int ticket = atomicInc(&g_done_count, NBLK - 1);
        s_is_last = (ticket == NBLK - 1);
    }
    __syncthreads();

    if (s_is_last) {
        // deterministic fixed-order reduction of 2048 per-row losses
        float lsum = 0.0f;
        #pragma unroll
        for (int k = 0; k < BATCH / 256; k++)
            lsum += g_row_loss[threadIdx.x + k * 256];

        #pragma unroll
        for (int off = 16; off > 0; off >>= 1)
            lsum += __shfl_down_sync(0xFFFFFFFFu, lsum, off);

        __shared__ float smem2[8];
        if (lane == 0) smem2[wid] = lsum;
        __syncthreads();
        if (threadIdx.x == 0) {
            loss[0] = smem2[0] + smem2[1] + smem2[2] + smem2[3]
                    + smem2[4] + smem2[5] + smem2[6] + smem2[7];
        }
    }
}

extern "C" void kernel_launch(void* const* d_in, const int* in_sizes, int n_in,
                              void* d_out, int out_size)
{
    // Inputs: 0 gate [2048,65536] f32, 1 sparse_bias [65536] f32,
    //         2 global_bias [1] f32, 3 label [2048] f32
    const float* gate  = (const float*)d_in[0];
    const float* bias  = (const float*)d_in[1];
    const float* gbias = (const float*)d_in[2];
    const float* label = (const float*)d_in[3];

    // Output: logits[2048], pred[2048], loss[1]
    float* out    = (float*)d_out;
    float* logits = out;
    float* pred   = out + BATCH;
    float* loss   = out + 2 * BATCH;

    fused_lr2_kernel<<<NBLK, 256>>>(gate, bias, gbias, label, logits, pred, loss);
}